// round 3
// baseline (speedup 1.0000x reference)
#include <cuda_runtime.h>

#define THREADS 448          // 14 warps; 98 rows = 14 * 7 exactly
#define N_TOK 98
#define CDIM 128
#define HEADS 4
#define LWIN 512

// smem layout (floats):
//  xs   [0      .. 12544)  : x tile 98x128, later reused as S (98 x stride 100)
//  q_s  [12544  .. 25088)  : 4 x 98 x 32  (later reused as O)
//  kT_s [25088  .. 37632)  : 4 x 32 x 98  (k transposed per head)
//  v_s  [37632  .. 50176)  : 4 x 98 x 32
//  wt   [50176  .. 54400)  : 128 x 33 (padded W tile, transposed)
#define SMEM_FLOATS 54400

__global__ __launch_bounds__(THREADS, 1)
void win_attn_kernel(const float* __restrict__ x,
                     const float* __restrict__ mask,
                     const float* __restrict__ qkv_w,
                     const float* __restrict__ qkv_b,
                     const float* __restrict__ pe,
                     const float* __restrict__ proj_w,
                     const float* __restrict__ proj_b,
                     float* __restrict__ out)
{
    extern __shared__ float sm[];
    float* xs   = sm;
    float* q_s  = sm + 12544;
    float* kT_s = sm + 25088;
    float* v_s  = sm + 37632;
    float* wt   = sm + 50176;

    const int b   = blockIdx.x;
    const int tid = threadIdx.x;
    const int tx  = tid & 31;
    const int ty  = tid >> 5;            // warp id 0..13
    const float scale = 0.17677669529663687f;  // 32^-0.5

    // ---------------- load x tile ----------------
    {
        const float4* xg4 = (const float4*)(x + (size_t)b * (N_TOK * CDIM));
        float4* xs4 = (float4*)xs;
        for (int i = tid; i < N_TOK * CDIM / 4; i += THREADS) xs4[i] = xg4[i];
    }
    __syncthreads();

    // ---------------- QKV GEMM: (98x128) @ (128x384)^T ----------------
    for (int ct = 0; ct < 12; ++ct) {
        // load 32-col W tile, transposed, pad-33 (conflict-free R/W)
        for (int idx = tid; idx < 32 * 128; idx += THREADS) {
            int cc = idx >> 7, kk = idx & 127;
            wt[kk * 33 + cc] = qkv_w[(ct * 32 + cc) * 128 + kk];
        }
        __syncthreads();

        float acc[7] = {0.f,0.f,0.f,0.f,0.f,0.f,0.f};
        const float4* xs4 = (const float4*)xs;
        #pragma unroll 4
        for (int k4 = 0; k4 < 32; ++k4) {
            float w0 = wt[(k4 * 4 + 0) * 33 + tx];
            float w1 = wt[(k4 * 4 + 1) * 33 + tx];
            float w2 = wt[(k4 * 4 + 2) * 33 + tx];
            float w3 = wt[(k4 * 4 + 3) * 33 + tx];
            #pragma unroll
            for (int r = 0; r < 7; ++r) {
                float4 a = xs4[(ty + 14 * r) * 32 + k4];
                acc[r] += a.x * w0 + a.y * w1 + a.z * w2 + a.w * w3;
            }
        }

        int c = ct * 32 + tx;
        float bias = qkv_b[c];
        int sec = c >> 7;            // 0=q 1=k 2=v
        int h   = (c >> 5) & 3;
        int d   = c & 31;
        #pragma unroll
        for (int r = 0; r < 7; ++r) {
            int i = ty + 14 * r;
            float v = acc[r] + bias;
            if (sec == 0)      q_s [h * 3136 + i * 32 + d] = v * scale;
            else if (sec == 1) kT_s[h * 3136 + d * 98 + i] = v;
            else               v_s [h * 3136 + i * 32 + d] = v;
        }
        __syncthreads();
    }

    // ---------------- attention, head-sequential ----------------
    const float* maskp = mask + (size_t)(b & (LWIN - 1)) * (N_TOK * N_TOK);
    float* S = xs;  // 98 rows, stride 100 (16B-aligned rows for float4)

    for (int h = 0; h < HEADS; ++h) {
        const float* qh  = q_s  + h * 3136;
        const float* kTh = kT_s + h * 3136;
        const float* vh  = v_s  + h * 3136;
        const float* peh = pe + h * 507;

        // ---- S = q k^T + bias + mask ----
        {
            float acc[7][4];
            #pragma unroll
            for (int r = 0; r < 7; ++r)
                #pragma unroll
                for (int jt = 0; jt < 4; ++jt) acc[r][jt] = 0.f;

            #pragma unroll 4
            for (int d = 0; d < 32; ++d) {
                float kv[4];
                #pragma unroll
                for (int jt = 0; jt < 4; ++jt) {
                    int j = tx + 32 * jt; int jc = j < 98 ? j : 97;
                    kv[jt] = kTh[d * 98 + jc];
                }
                #pragma unroll
                for (int r = 0; r < 7; ++r) {
                    float qv = qh[(ty + 14 * r) * 32 + d];
                    #pragma unroll
                    for (int jt = 0; jt < 4; ++jt) acc[r][jt] += qv * kv[jt];
                }
            }

            #pragma unroll
            for (int r = 0; r < 7; ++r) {
                int i = ty + 14 * r;
                int ti = i / 49, rem = i % 49, hi = rem / 7, wi = rem % 7;
                int base = (ti + 1) * 169 + (hi + 6) * 13 + (wi + 6);
                #pragma unroll
                for (int jt = 0; jt < 4; ++jt) {
                    int j = tx + 32 * jt;
                    if (j >= 98) continue;
                    int tj = j / 49, remj = j % 49, hj = remj / 7, wj = remj % 7;
                    int ridx = base - tj * 169 - hj * 13 - wj;
                    S[i * 100 + j] = acc[r][jt] + peh[ridx] + maskp[i * 98 + j];
                }
            }
        }
        __syncthreads();

        // ---- softmax: warp ty handles rows ty, ty+14, ... ----
        #pragma unroll
        for (int r = 0; r < 7; ++r) {
            int i = ty + 14 * r;
            float vals[4]; float m = -1e30f;
            #pragma unroll
            for (int jt = 0; jt < 4; ++jt) {
                int j = tx + 32 * jt;
                vals[jt] = (j < 98) ? S[i * 100 + j] : -1e30f;
                m = fmaxf(m, vals[jt]);
            }
            #pragma unroll
            for (int o = 16; o > 0; o >>= 1) m = fmaxf(m, __shfl_xor_sync(0xffffffffu, m, o));
            float ssum = 0.f;
            #pragma unroll
            for (int jt = 0; jt < 4; ++jt) {
                int j = tx + 32 * jt;
                float p = (j < 98) ? __expf(vals[jt] - m) : 0.f;
                vals[jt] = p; ssum += p;
            }
            #pragma unroll
            for (int o = 16; o > 0; o >>= 1) ssum += __shfl_xor_sync(0xffffffffu, ssum, o);
            float inv = 1.f / ssum;
            #pragma unroll
            for (int jt = 0; jt < 4; ++jt) {
                int j = tx + 32 * jt;
                if (j < 98) S[i * 100 + j] = vals[jt] * inv;
            }
        }
        __syncthreads();

        // ---- O = P @ V  (thread: col d = tx, rows i = ty+14r) ----
        float oacc[7] = {0.f,0.f,0.f,0.f,0.f,0.f,0.f};
        for (int t = 0; t < 6; ++t) {
            int j0 = t * 16;
            float vv[16];
            #pragma unroll
            for (int u = 0; u < 16; ++u) vv[u] = vh[(j0 + u) * 32 + tx];
            #pragma unroll
            for (int r = 0; r < 7; ++r) {
                const float4* p4 = (const float4*)(S + (ty + 14 * r) * 100 + j0);
                #pragma unroll
                for (int u4 = 0; u4 < 4; ++u4) {
                    float4 p = p4[u4];
                    oacc[r] += p.x * vv[u4*4+0] + p.y * vv[u4*4+1]
                             + p.z * vv[u4*4+2] + p.w * vv[u4*4+3];
                }
            }
        }
        {   // tail j = 96..97 (only .x/.y of the float4 are consumed)
            float vv0 = vh[96 * 32 + tx], vv1 = vh[97 * 32 + tx];
            #pragma unroll
            for (int r = 0; r < 7; ++r) {
                float4 p = *(const float4*)(S + (ty + 14 * r) * 100 + 96);
                oacc[r] += p.x * vv0 + p.y * vv1;
            }
        }
        // write O into the (now dead) q slot of this head: O[i][h*32+d]
        #pragma unroll
        for (int r = 0; r < 7; ++r)
            q_s[h * 3136 + (ty + 14 * r) * 32 + tx] = oacc[r];
        __syncthreads();   // protect S overwrite by next head / proj
    }

    // ---------------- projection: out = O @ proj_w^T + proj_b ----------------
    for (int ct = 0; ct < 4; ++ct) {
        for (int idx = tid; idx < 32 * 128; idx += THREADS) {
            int cc = idx >> 7, kk = idx & 127;
            wt[kk * 33 + cc] = proj_w[(ct * 32 + cc) * 128 + kk];
        }
        __syncthreads();

        float acc[7] = {0.f,0.f,0.f,0.f,0.f,0.f,0.f};
        #pragma unroll
        for (int kh = 0; kh < 4; ++kh) {
            const float4* A4 = (const float4*)(q_s + kh * 3136);
            #pragma unroll 2
            for (int k4 = 0; k4 < 8; ++k4) {
                float w0 = wt[(kh * 32 + k4 * 4 + 0) * 33 + tx];
                float w1 = wt[(kh * 32 + k4 * 4 + 1) * 33 + tx];
                float w2 = wt[(kh * 32 + k4 * 4 + 2) * 33 + tx];
                float w3 = wt[(kh * 32 + k4 * 4 + 3) * 33 + tx];
                #pragma unroll
                for (int r = 0; r < 7; ++r) {
                    float4 a = A4[(ty + 14 * r) * 8 + k4];
                    acc[r] += a.x * w0 + a.y * w1 + a.z * w2 + a.w * w3;
                }
            }
        }
        int c = ct * 32 + tx;
        float pb = proj_b[c];
        #pragma unroll
        for (int r = 0; r < 7; ++r) {
            int i = ty + 14 * r;
            out[(size_t)b * (N_TOK * CDIM) + i * 128 + c] = acc[r] + pb;
        }
        __syncthreads();   // wt reload safety for next tile
    }
}

extern "C" void kernel_launch(void* const* d_in, const int* in_sizes, int n_in,
                              void* d_out, int out_size)
{
    const float* x      = (const float*)d_in[0];
    const float* mask   = (const float*)d_in[1];
    const float* qkv_w  = (const float*)d_in[2];
    const float* qkv_b  = (const float*)d_in[3];
    const float* pe     = (const float*)d_in[4];
    const float* proj_w = (const float*)d_in[5];
    const float* proj_b = (const float*)d_in[6];
    float* out = (float*)d_out;

    const int smem_bytes = SMEM_FLOATS * sizeof(float);   // 217600
    cudaFuncSetAttribute(win_attn_kernel,
                         cudaFuncAttributeMaxDynamicSharedMemorySize, smem_bytes);

    int nwin = in_sizes[0] / (N_TOK * CDIM);              // 2048
    win_attn_kernel<<<nwin, THREADS, smem_bytes>>>(
        x, mask, qkv_w, qkv_b, pe, proj_w, proj_b, out);
}

// round 5
// speedup vs baseline: 1.4812x; 1.4812x over previous
#include <cuda_runtime.h>

#define THREADS 448          // 14 warps; 98 rows = 14 * 7 exactly
#define N_TOK 98
#define CDIM 128
#define HEADS 4
#define LWIN 512

// smem layout (floats):
//  xs   [0      .. 12544)  : x tile 98x128; later reused as S (98 rows, stride 100)
//  q_s  [12544  .. 25088)  : 4 x 98 x 32  (later reused as O)
//  kT_s [25088  .. 37760)  : 4 x 32 x 99  (k transposed per head, stride 99)
//  v_s  [37760  .. 50304)  : 4 x 98 x 32
//  wt   [50304  .. 54432)  : 32 x 129    (w chunk: wt[k][c], pad-129)
#define SMEM_FLOATS 54432

__global__ __launch_bounds__(THREADS, 1)
void win_attn_kernel(const float* __restrict__ x,
                     const float* __restrict__ mask,
                     const float* __restrict__ qkv_w,
                     const float* __restrict__ qkv_b,
                     const float* __restrict__ pe,
                     const float* __restrict__ proj_w,
                     const float* __restrict__ proj_b,
                     float* __restrict__ out)
{
    extern __shared__ float sm[];
    float* xs   = sm;
    float* q_s  = sm + 12544;
    float* kT_s = sm + 25088;
    float* v_s  = sm + 37760;
    float* wt   = sm + 50304;

    const int b   = blockIdx.x;
    const int tid = threadIdx.x;
    const int tx  = tid & 31;
    const int ty  = tid >> 5;            // warp id 0..13
    const float scale = 0.17677669529663687f;  // 32^-0.5

    // ---------------- load x tile ----------------
    {
        const float4* xg4 = (const float4*)(x + (size_t)b * (N_TOK * CDIM));
        float4* xs4 = (float4*)xs;
        for (int i = tid; i < N_TOK * CDIM / 4; i += THREADS) xs4[i] = xg4[i];
    }

    // ---------------- QKV GEMM: (98x128) @ (128x384)^T ----------------
    // sect 0 = q, 1 = k, 2 = v. Lane owns cols c = tx + 32m (h = m, d = tx).
    // Warp owns rows i = ty + 14r -> activation loads are warp-broadcast.
    for (int sect = 0; sect < 3; ++sect) {
        float acc[7][4];
        #pragma unroll
        for (int r = 0; r < 7; ++r)
            #pragma unroll
            for (int m = 0; m < 4; ++m) acc[r][m] = 0.f;

        for (int kc = 0; kc < 4; ++kc) {
            __syncthreads();   // previous wt use (or x-tile load) complete
            // wt[kk][cc] = W[sect*128+cc][kc*32+kk]; coalesced read, conflict-free write
            for (int idx = tid; idx < 32 * 128; idx += THREADS) {
                int kk = idx & 31, cc = idx >> 5;
                wt[kk * 129 + cc] = qkv_w[(sect * 128 + cc) * 128 + kc * 32 + kk];
            }
            __syncthreads();

            const float4* xs4 = (const float4*)xs;
            #pragma unroll
            for (int k4 = 0; k4 < 8; ++k4) {
                float4 a[7];                       // broadcast loads (lane-uniform addr)
                #pragma unroll
                for (int r = 0; r < 7; ++r)
                    a[r] = xs4[(ty + 14 * r) * 32 + kc * 8 + k4];
                #pragma unroll
                for (int u = 0; u < 4; ++u) {
                    int kk = k4 * 4 + u;
                    float w0 = wt[kk * 129 + tx];
                    float w1 = wt[kk * 129 + tx + 32];
                    float w2 = wt[kk * 129 + tx + 64];
                    float w3 = wt[kk * 129 + tx + 96];
                    #pragma unroll
                    for (int r = 0; r < 7; ++r) {
                        float av = (u == 0) ? a[r].x : (u == 1) ? a[r].y
                                 : (u == 2) ? a[r].z : a[r].w;
                        acc[r][0] += av * w0;
                        acc[r][1] += av * w1;
                        acc[r][2] += av * w2;
                        acc[r][3] += av * w3;
                    }
                }
            }
        }

        // epilogue: h = m, d = tx
        #pragma unroll
        for (int m = 0; m < 4; ++m) {
            float bias = qkv_b[sect * 128 + tx + 32 * m];
            #pragma unroll
            for (int r = 0; r < 7; ++r) {
                int i = ty + 14 * r;
                float v = acc[r][m] + bias;
                if (sect == 0)      q_s [m * 3136 + i * 32 + tx] = v * scale;
                else if (sect == 1) kT_s[m * 3168 + tx * 99 + i] = v;   // conflict-free
                else                v_s [m * 3136 + i * 32 + tx] = v;
            }
        }
    }
    __syncthreads();   // q/kT/v complete; xs free for reuse as S

    // ---------------- attention, head-sequential ----------------
    const float* maskp = mask + (size_t)(b & (LWIN - 1)) * (N_TOK * N_TOK);
    float* S = xs;  // 98 rows, stride 100 (16B-aligned rows for float4)

    // per-lane j decompositions (loop-invariant)
    int jofs[4];
    #pragma unroll
    for (int jt = 0; jt < 4; ++jt) {
        int j = tx + 32 * jt;
        int jc = j < 98 ? j : 97;
        int tj = jc / 49, remj = jc % 49, hj = remj / 7, wj = remj % 7;
        jofs[jt] = tj * 169 + hj * 13 + wj;
    }

    for (int h = 0; h < HEADS; ++h) {
        const float* qh  = q_s  + h * 3136;
        const float* kTh = kT_s + h * 3168;
        const float* vh  = v_s  + h * 3136;
        const float* peh = pe + h * 507;

        // ---- S = q k^T + bias + mask ----
        {
            float acc[7][4];
            #pragma unroll
            for (int r = 0; r < 7; ++r)
                #pragma unroll
                for (int jt = 0; jt < 4; ++jt) acc[r][jt] = 0.f;

            #pragma unroll
            for (int d4 = 0; d4 < 8; ++d4) {
                float4 qv[7];                      // broadcast loads
                #pragma unroll
                for (int r = 0; r < 7; ++r)
                    qv[r] = ((const float4*)(qh + (ty + 14 * r) * 32))[d4];
                #pragma unroll
                for (int u = 0; u < 4; ++u) {
                    int d = d4 * 4 + u;
                    float kv[4];
                    #pragma unroll
                    for (int jt = 0; jt < 4; ++jt) {
                        int j = tx + 32 * jt; int jc = j < 98 ? j : 97;
                        kv[jt] = kTh[d * 99 + jc];
                    }
                    #pragma unroll
                    for (int r = 0; r < 7; ++r) {
                        float qc = (u == 0) ? qv[r].x : (u == 1) ? qv[r].y
                                 : (u == 2) ? qv[r].z : qv[r].w;
                        acc[r][0] += qc * kv[0];
                        acc[r][1] += qc * kv[1];
                        acc[r][2] += qc * kv[2];
                        acc[r][3] += qc * kv[3];
                    }
                }
            }

            #pragma unroll
            for (int r = 0; r < 7; ++r) {
                int i = ty + 14 * r;
                int ti = i / 49, rem = i % 49, hi = rem / 7, wi = rem % 7;
                int base = (ti + 1) * 169 + (hi + 6) * 13 + (wi + 6);
                const float* mrow = maskp + i * 98;
                float* srow = S + i * 100;
                #pragma unroll
                for (int jt = 0; jt < 4; ++jt) {
                    int j = tx + 32 * jt;
                    if (j >= 98) continue;
                    srow[j] = acc[r][jt] + peh[base - jofs[jt]] + mrow[j];
                }
            }
        }
        __syncthreads();

        // ---- softmax: warp ty handles rows ty, ty+14, ... ----
        #pragma unroll
        for (int r = 0; r < 7; ++r) {
            int i = ty + 14 * r;
            float vals[4]; float m = -1e30f;
            #pragma unroll
            for (int jt = 0; jt < 4; ++jt) {
                int j = tx + 32 * jt;
                vals[jt] = (j < 98) ? S[i * 100 + j] : -1e30f;
                m = fmaxf(m, vals[jt]);
            }
            #pragma unroll
            for (int o = 16; o > 0; o >>= 1) m = fmaxf(m, __shfl_xor_sync(0xffffffffu, m, o));
            float ssum = 0.f;
            #pragma unroll
            for (int jt = 0; jt < 4; ++jt) {
                int j = tx + 32 * jt;
                float p = (j < 98) ? __expf(vals[jt] - m) : 0.f;
                vals[jt] = p; ssum += p;
            }
            #pragma unroll
            for (int o = 16; o > 0; o >>= 1) ssum += __shfl_xor_sync(0xffffffffu, ssum, o);
            float inv = 1.f / ssum;
            #pragma unroll
            for (int jt = 0; jt < 4; ++jt) {
                int j = tx + 32 * jt;
                if (j < 98) S[i * 100 + j] = vals[jt] * inv;
            }
        }
        __syncthreads();

        // ---- O = P @ V  (thread: col d = tx, rows i = ty+14r) ----
        float oacc[7] = {0.f,0.f,0.f,0.f,0.f,0.f,0.f};
        for (int t = 0; t < 6; ++t) {
            int j0 = t * 16;
            float vv[16];
            #pragma unroll
            for (int u = 0; u < 16; ++u) vv[u] = vh[(j0 + u) * 32 + tx];
            #pragma unroll
            for (int r = 0; r < 7; ++r) {
                const float4* p4 = (const float4*)(S + (ty + 14 * r) * 100 + j0);
                #pragma unroll
                for (int u4 = 0; u4 < 4; ++u4) {
                    float4 p = p4[u4];
                    oacc[r] += p.x * vv[u4*4+0] + p.y * vv[u4*4+1]
                             + p.z * vv[u4*4+2] + p.w * vv[u4*4+3];
                }
            }
        }
        {   // tail j = 96..97 (only .x/.y of the float4 are consumed)
            float vv0 = vh[96 * 32 + tx], vv1 = vh[97 * 32 + tx];
            #pragma unroll
            for (int r = 0; r < 7; ++r) {
                float4 p = *(const float4*)(S + (ty + 14 * r) * 100 + 96);
                oacc[r] += p.x * vv0 + p.y * vv1;
            }
        }
        // write O into the (now dead) q slot of this head: O[i][h*32+d]
        #pragma unroll
        for (int r = 0; r < 7; ++r)
            q_s[h * 3136 + (ty + 14 * r) * 32 + tx] = oacc[r];
        __syncthreads();   // protect S overwrite by next head / proj
    }

    // ---------------- projection: out = O @ proj_w^T + proj_b ----------------
    // Same mapping as QKV. k-chunk kc == head kc, so O float4 loads come
    // straight from q_s + kc*3136.
    {
        float acc[7][4];
        #pragma unroll
        for (int r = 0; r < 7; ++r)
            #pragma unroll
            for (int m = 0; m < 4; ++m) acc[r][m] = 0.f;

        for (int kc = 0; kc < 4; ++kc) {
            __syncthreads();
            for (int idx = tid; idx < 32 * 128; idx += THREADS) {
                int kk = idx & 31, cc = idx >> 5;
                wt[kk * 129 + cc] = proj_w[cc * 128 + kc * 32 + kk];
            }
            __syncthreads();

            const float4* O4 = (const float4*)(q_s + kc * 3136);
            #pragma unroll
            for (int k4 = 0; k4 < 8; ++k4) {
                float4 a[7];                       // broadcast loads
                #pragma unroll
                for (int r = 0; r < 7; ++r)
                    a[r] = O4[(ty + 14 * r) * 8 + k4];
                #pragma unroll
                for (int u = 0; u < 4; ++u) {
                    int kk = k4 * 4 + u;
                    float w0 = wt[kk * 129 + tx];
                    float w1 = wt[kk * 129 + tx + 32];
                    float w2 = wt[kk * 129 + tx + 64];
                    float w3 = wt[kk * 129 + tx + 96];
                    #pragma unroll
                    for (int r = 0; r < 7; ++r) {
                        float av = (u == 0) ? a[r].x : (u == 1) ? a[r].y
                                 : (u == 2) ? a[r].z : a[r].w;
                        acc[r][0] += av * w0;
                        acc[r][1] += av * w1;
                        acc[r][2] += av * w2;
                        acc[r][3] += av * w3;
                    }
                }
            }
        }

        #pragma unroll
        for (int m = 0; m < 4; ++m) {
            float pb = proj_b[tx + 32 * m];
            #pragma unroll
            for (int r = 0; r < 7; ++r) {
                int i = ty + 14 * r;
                out[(size_t)b * (N_TOK * CDIM) + i * 128 + tx + 32 * m] = acc[r][m] + pb;
            }
        }
    }
}

extern "C" void kernel_launch(void* const* d_in, const int* in_sizes, int n_in,
                              void* d_out, int out_size)
{
    const float* x      = (const float*)d_in[0];
    const float* mask   = (const float*)d_in[1];
    const float* qkv_w  = (const float*)d_in[2];
    const float* qkv_b  = (const float*)d_in[3];
    const float* pe     = (const float*)d_in[4];
    const float* proj_w = (const float*)d_in[5];
    const float* proj_b = (const float*)d_in[6];
    float* out = (float*)d_out;

    const int smem_bytes = SMEM_FLOATS * sizeof(float);   // 217728
    cudaFuncSetAttribute(win_attn_kernel,
                         cudaFuncAttributeMaxDynamicSharedMemorySize, smem_bytes);

    int nwin = in_sizes[0] / (N_TOK * CDIM);              // 2048
    win_attn_kernel<<<nwin, THREADS, smem_bytes>>>(
        x, mask, qkv_w, qkv_b, pe, proj_w, proj_b, out);
}

// round 6
// speedup vs baseline: 1.5424x; 1.0413x over previous
#include <cuda_runtime.h>

#define THREADS 448          // 14 warps; 98 rows = 14 * 7 exactly
#define N_TOK 98
#define CDIM 128
#define HEADS 4
#define LWIN 512

// packed f32x2 helpers (carrier = unsigned long long)
#define PACK2(d, lo, hi)   asm("mov.b64 %0, {%1, %2};" : "=l"(d) : "f"(lo), "f"(hi))
#define UNPACK2(lo, hi, s) asm("mov.b64 {%0, %1}, %2;" : "=f"(lo), "=f"(hi) : "l"(s))
#define FMA2(d, a, b, c)   asm("fma.rn.f32x2 %0, %1, %2, %3;" : "=l"(d) : "l"(a), "l"(b), "l"(c))

// smem layout (floats):
//  xs   [0      .. 12544)  : x tile 98x128; later reused as S (98 rows, stride 100)
//  q_s  [12544  .. 25088)  : 4 x 98 x 32  (later reused as O)
//  kT_s [25088  .. 37760)  : 4 x 32 x 99  (k transposed per head, stride 99)
//  v_s  [37760  .. 50304)  : 4 x 98 x 32
//  wt   [50304  .. 54592)  : 32 x 134    paired w tile: row kk holds
//                            [(c,c+32) pairs at +2*pos][(c+64,c+96) pairs at +66]
#define SMEM_FLOATS 54592

// precomputed rel-pos bias table: bias[h][i][j]
__device__ float g_bias[HEADS * N_TOK * N_TOK];

__global__ void bias_precompute_kernel(const float* __restrict__ pe)
{
    int idx = blockIdx.x * blockDim.x + threadIdx.x;
    if (idx >= HEADS * N_TOK * N_TOK) return;
    int h = idx / (N_TOK * N_TOK);
    int r = idx % (N_TOK * N_TOK);
    int i = r / N_TOK, j = r % N_TOK;
    int ti = i / 49, rem = i % 49, hi = rem / 7, wi = rem % 7;
    int tj = j / 49, remj = j % 49, hj = remj / 7, wj = remj % 7;
    int ridx = (ti - tj + 1) * 169 + (hi - hj + 6) * 13 + (wi - wj + 6);
    g_bias[idx] = pe[h * 507 + ridx];
}

__global__ __launch_bounds__(THREADS, 1)
void win_attn_kernel(const float* __restrict__ x,
                     const float* __restrict__ mask,
                     const float* __restrict__ qkv_w,
                     const float* __restrict__ qkv_b,
                     const float* __restrict__ proj_w,
                     const float* __restrict__ proj_b,
                     float* __restrict__ out)
{
    extern __shared__ float sm[];
    float* xs   = sm;
    float* q_s  = sm + 12544;
    float* kT_s = sm + 25088;
    float* v_s  = sm + 37760;
    float* wt   = sm + 50304;

    const int b   = blockIdx.x;
    const int tid = threadIdx.x;
    const int tx  = tid & 31;
    const int ty  = tid >> 5;            // warp id 0..13
    const float scale = 0.17677669529663687f;  // 32^-0.5

    // ---------------- load x tile ----------------
    {
        const float4* xg4 = (const float4*)(x + (size_t)b * (N_TOK * CDIM));
        float4* xs4 = (float4*)xs;
        for (int i = tid; i < N_TOK * CDIM / 4; i += THREADS) xs4[i] = xg4[i];
    }

    // ---------------- QKV GEMM: (98x128) @ (128x384)^T ----------------
    // Lane owns cols c = tx+32m packed as (m0,m1),(m2,m3); warp owns rows i=ty+14r.
    for (int sect = 0; sect < 3; ++sect) {
        unsigned long long acc2[7][2];
        #pragma unroll
        for (int r = 0; r < 7; ++r) { acc2[r][0] = 0ull; acc2[r][1] = 0ull; }

        for (int kc = 0; kc < 4; ++kc) {
            __syncthreads();   // previous wt use (or x-tile load) complete
            // paired layout: wt[kk*134 + (grp>>1)*66 + pos*2 + (grp&1)]
            for (int idx = tid; idx < 32 * 128; idx += THREADS) {
                int kk = idx & 31, cc = idx >> 5;
                int pos = cc & 31, grp = cc >> 5;
                wt[kk * 134 + (grp >> 1) * 66 + pos * 2 + (grp & 1)]
                    = qkv_w[(sect * 128 + cc) * 128 + kc * 32 + kk];
            }
            __syncthreads();

            const float4* xs4 = (const float4*)xs;
            #pragma unroll
            for (int k4 = 0; k4 < 8; ++k4) {
                float4 a[7];                       // broadcast loads (lane-uniform addr)
                #pragma unroll
                for (int r = 0; r < 7; ++r)
                    a[r] = xs4[(ty + 14 * r) * 32 + kc * 8 + k4];
                #pragma unroll
                for (int u = 0; u < 4; ++u) {
                    int kk = k4 * 4 + u;
                    unsigned long long wA = *(const unsigned long long*)(wt + kk * 134 + tx * 2);
                    unsigned long long wB = *(const unsigned long long*)(wt + kk * 134 + 66 + tx * 2);
                    #pragma unroll
                    for (int r = 0; r < 7; ++r) {
                        float av = (u == 0) ? a[r].x : (u == 1) ? a[r].y
                                 : (u == 2) ? a[r].z : a[r].w;
                        unsigned long long avd;
                        PACK2(avd, av, av);
                        FMA2(acc2[r][0], avd, wA, acc2[r][0]);
                        FMA2(acc2[r][1], avd, wB, acc2[r][1]);
                    }
                }
            }
        }

        // epilogue: unpack; h = m, d = tx
        float bias0 = qkv_b[sect * 128 + tx];
        float bias1 = qkv_b[sect * 128 + tx + 32];
        float bias2 = qkv_b[sect * 128 + tx + 64];
        float bias3 = qkv_b[sect * 128 + tx + 96];
        #pragma unroll
        for (int r = 0; r < 7; ++r) {
            int i = ty + 14 * r;
            float v0, v1, v2, v3;
            UNPACK2(v0, v1, acc2[r][0]);
            UNPACK2(v2, v3, acc2[r][1]);
            v0 += bias0; v1 += bias1; v2 += bias2; v3 += bias3;
            if (sect == 0) {
                q_s[0 * 3136 + i * 32 + tx] = v0 * scale;
                q_s[1 * 3136 + i * 32 + tx] = v1 * scale;
                q_s[2 * 3136 + i * 32 + tx] = v2 * scale;
                q_s[3 * 3136 + i * 32 + tx] = v3 * scale;
            } else if (sect == 1) {
                kT_s[0 * 3168 + tx * 99 + i] = v0;
                kT_s[1 * 3168 + tx * 99 + i] = v1;
                kT_s[2 * 3168 + tx * 99 + i] = v2;
                kT_s[3 * 3168 + tx * 99 + i] = v3;
            } else {
                v_s[0 * 3136 + i * 32 + tx] = v0;
                v_s[1 * 3136 + i * 32 + tx] = v1;
                v_s[2 * 3136 + i * 32 + tx] = v2;
                v_s[3 * 3136 + i * 32 + tx] = v3;
            }
        }
    }
    __syncthreads();   // q/kT/v complete; xs free for reuse as S

    // ---------------- attention, head-sequential ----------------
    const float* maskp = mask + (size_t)(b & (LWIN - 1)) * (N_TOK * N_TOK);
    float* S = xs;  // 98 rows, stride 100 (16B-aligned rows)

    for (int h = 0; h < HEADS; ++h) {
        const float* qh  = q_s  + h * 3136;
        const float* kTh = kT_s + h * 3168;
        const float* vh  = v_s  + h * 3136;
        const float* bh  = g_bias + h * (N_TOK * N_TOK);

        // ---- S = q k^T + bias + mask ---- (packed over (jt0,jt1),(jt2,jt3))
        {
            unsigned long long acc2[7][2];
            #pragma unroll
            for (int r = 0; r < 7; ++r) { acc2[r][0] = 0ull; acc2[r][1] = 0ull; }

            #pragma unroll
            for (int d4 = 0; d4 < 8; ++d4) {
                float4 qv[7];                      // broadcast loads
                #pragma unroll
                for (int r = 0; r < 7; ++r)
                    qv[r] = ((const float4*)(qh + (ty + 14 * r) * 32))[d4];
                #pragma unroll
                for (int u = 0; u < 4; ++u) {
                    int d = d4 * 4 + u;
                    int j3 = tx + 96; j3 = j3 < 98 ? j3 : 97;
                    float kv0 = kTh[d * 99 + tx];
                    float kv1 = kTh[d * 99 + tx + 32];
                    float kv2 = kTh[d * 99 + tx + 64];
                    float kv3 = kTh[d * 99 + j3];
                    unsigned long long kvA, kvB;
                    PACK2(kvA, kv0, kv1);
                    PACK2(kvB, kv2, kv3);
                    #pragma unroll
                    for (int r = 0; r < 7; ++r) {
                        float qc = (u == 0) ? qv[r].x : (u == 1) ? qv[r].y
                                 : (u == 2) ? qv[r].z : qv[r].w;
                        unsigned long long qd;
                        PACK2(qd, qc, qc);
                        FMA2(acc2[r][0], qd, kvA, acc2[r][0]);
                        FMA2(acc2[r][1], qd, kvB, acc2[r][1]);
                    }
                }
            }

            #pragma unroll
            for (int r = 0; r < 7; ++r) {
                int i = ty + 14 * r;
                const float* mrow = maskp + i * 98;
                const float* brow = bh + i * 98;
                float* srow = S + i * 100;
                float s0, s1, s2, s3;
                UNPACK2(s0, s1, acc2[r][0]);
                UNPACK2(s2, s3, acc2[r][1]);
                srow[tx]      = s0 + brow[tx]      + mrow[tx];
                srow[tx + 32] = s1 + brow[tx + 32] + mrow[tx + 32];
                srow[tx + 64] = s2 + brow[tx + 64] + mrow[tx + 64];
                if (tx < 2)
                    srow[tx + 96] = s3 + brow[tx + 96] + mrow[tx + 96];
            }
        }
        __syncthreads();

        // ---- softmax: warp ty handles rows ty, ty+14, ... ----
        #pragma unroll
        for (int r = 0; r < 7; ++r) {
            int i = ty + 14 * r;
            float vals[4]; float m = -1e30f;
            #pragma unroll
            for (int jt = 0; jt < 4; ++jt) {
                int j = tx + 32 * jt;
                vals[jt] = (j < 98) ? S[i * 100 + j] : -1e30f;
                m = fmaxf(m, vals[jt]);
            }
            #pragma unroll
            for (int o = 16; o > 0; o >>= 1) m = fmaxf(m, __shfl_xor_sync(0xffffffffu, m, o));
            float ssum = 0.f;
            #pragma unroll
            for (int jt = 0; jt < 4; ++jt) {
                int j = tx + 32 * jt;
                float p = (j < 98) ? __expf(vals[jt] - m) : 0.f;
                vals[jt] = p; ssum += p;
            }
            #pragma unroll
            for (int o = 16; o > 0; o >>= 1) ssum += __shfl_xor_sync(0xffffffffu, ssum, o);
            float inv = 1.f / ssum;
            #pragma unroll
            for (int jt = 0; jt < 4; ++jt) {
                int j = tx + 32 * jt;
                if (j < 98) S[i * 100 + j] = vals[jt] * inv;
            }
        }
        __syncthreads();

        // ---- O = P @ V  packed: even/odd-j partial sums, reduced at end ----
        unsigned long long oacc2[7];
        #pragma unroll
        for (int r = 0; r < 7; ++r) oacc2[r] = 0ull;

        for (int t = 0; t < 6; ++t) {
            int j0 = t * 16;
            unsigned long long vpk[8];
            #pragma unroll
            for (int u = 0; u < 8; ++u) {
                float v0 = vh[(j0 + 2 * u)     * 32 + tx];
                float v1 = vh[(j0 + 2 * u + 1) * 32 + tx];
                PACK2(vpk[u], v0, v1);
            }
            #pragma unroll
            for (int r = 0; r < 7; ++r) {
                const ulonglong2* p2 = (const ulonglong2*)(S + (ty + 14 * r) * 100 + j0);
                #pragma unroll
                for (int q4 = 0; q4 < 4; ++q4) {
                    ulonglong2 pp = p2[q4];           // 4 packed P values
                    FMA2(oacc2[r], pp.x, vpk[2 * q4],     oacc2[r]);
                    FMA2(oacc2[r], pp.y, vpk[2 * q4 + 1], oacc2[r]);
                }
            }
        }
        {   // tail j = 96..97
            float v0 = vh[96 * 32 + tx], v1 = vh[97 * 32 + tx];
            unsigned long long vt;
            PACK2(vt, v0, v1);
            #pragma unroll
            for (int r = 0; r < 7; ++r) {
                unsigned long long pt = *(const unsigned long long*)(S + (ty + 14 * r) * 100 + 96);
                FMA2(oacc2[r], pt, vt, oacc2[r]);
            }
        }
        // reduce packed halves, write O into the dead q slot: O[i][h*32+d]
        #pragma unroll
        for (int r = 0; r < 7; ++r) {
            float lo, hi;
            UNPACK2(lo, hi, oacc2[r]);
            q_s[h * 3136 + (ty + 14 * r) * 32 + tx] = lo + hi;
        }
        __syncthreads();   // protect S overwrite by next head / proj
    }

    // ---------------- projection: out = O @ proj_w^T + proj_b ----------------
    {
        unsigned long long acc2[7][2];
        #pragma unroll
        for (int r = 0; r < 7; ++r) { acc2[r][0] = 0ull; acc2[r][1] = 0ull; }

        for (int kc = 0; kc < 4; ++kc) {
            __syncthreads();
            for (int idx = tid; idx < 32 * 128; idx += THREADS) {
                int kk = idx & 31, cc = idx >> 5;
                int pos = cc & 31, grp = cc >> 5;
                wt[kk * 134 + (grp >> 1) * 66 + pos * 2 + (grp & 1)]
                    = proj_w[cc * 128 + kc * 32 + kk];
            }
            __syncthreads();

            const float4* O4 = (const float4*)(q_s + kc * 3136);
            #pragma unroll
            for (int k4 = 0; k4 < 8; ++k4) {
                float4 a[7];                       // broadcast loads
                #pragma unroll
                for (int r = 0; r < 7; ++r)
                    a[r] = O4[(ty + 14 * r) * 8 + k4];
                #pragma unroll
                for (int u = 0; u < 4; ++u) {
                    int kk = k4 * 4 + u;
                    unsigned long long wA = *(const unsigned long long*)(wt + kk * 134 + tx * 2);
                    unsigned long long wB = *(const unsigned long long*)(wt + kk * 134 + 66 + tx * 2);
                    #pragma unroll
                    for (int r = 0; r < 7; ++r) {
                        float av = (u == 0) ? a[r].x : (u == 1) ? a[r].y
                                 : (u == 2) ? a[r].z : a[r].w;
                        unsigned long long avd;
                        PACK2(avd, av, av);
                        FMA2(acc2[r][0], avd, wA, acc2[r][0]);
                        FMA2(acc2[r][1], avd, wB, acc2[r][1]);
                    }
                }
            }
        }

        float pb0 = proj_b[tx];
        float pb1 = proj_b[tx + 32];
        float pb2 = proj_b[tx + 64];
        float pb3 = proj_b[tx + 96];
        #pragma unroll
        for (int r = 0; r < 7; ++r) {
            int i = ty + 14 * r;
            float v0, v1, v2, v3;
            UNPACK2(v0, v1, acc2[r][0]);
            UNPACK2(v2, v3, acc2[r][1]);
            float* orow = out + (size_t)b * (N_TOK * CDIM) + i * 128;
            orow[tx]      = v0 + pb0;
            orow[tx + 32] = v1 + pb1;
            orow[tx + 64] = v2 + pb2;
            orow[tx + 96] = v3 + pb3;
        }
    }
}

extern "C" void kernel_launch(void* const* d_in, const int* in_sizes, int n_in,
                              void* d_out, int out_size)
{
    const float* x      = (const float*)d_in[0];
    const float* mask   = (const float*)d_in[1];
    const float* qkv_w  = (const float*)d_in[2];
    const float* qkv_b  = (const float*)d_in[3];
    const float* pe     = (const float*)d_in[4];
    const float* proj_w = (const float*)d_in[5];
    const float* proj_b = (const float*)d_in[6];
    float* out = (float*)d_out;

    // expand rel-pos bias into g_bias (153 KB, L2-resident)
    bias_precompute_kernel<<<(HEADS * N_TOK * N_TOK + 255) / 256, 256>>>(pe);

    const int smem_bytes = SMEM_FLOATS * sizeof(float);   // 218368
    cudaFuncSetAttribute(win_attn_kernel,
                         cudaFuncAttributeMaxDynamicSharedMemorySize, smem_bytes);

    int nwin = in_sizes[0] / (N_TOK * CDIM);              // 2048
    win_attn_kernel<<<nwin, THREADS, smem_bytes>>>(
        x, mask, qkv_w, qkv_b, proj_w, proj_b, out);
}

// round 7
// speedup vs baseline: 2.0619x; 1.3368x over previous
#include <cuda_runtime.h>

#define THREADS 512          // 16 warps
#define N_TOK 98
#define CDIM 128
#define HEADS 4
#define LWIN 512

// packed f32x2 helpers (carrier = unsigned long long)
#define PACK2(d, lo, hi)   asm("mov.b64 %0, {%1, %2};" : "=l"(d) : "f"(lo), "f"(hi))
#define UNPACK2(lo, hi, s) asm("mov.b64 {%0, %1}, %2;" : "=f"(lo), "=f"(hi) : "l"(s))
#define FMA2(d, a, b, c)   asm("fma.rn.f32x2 %0, %1, %2, %3;" : "=l"(d) : "l"(a), "l"(b), "l"(c))
#define CVT_TF32(u, f)     asm("cvt.rna.tf32.f32 %0, %1;" : "=r"(u) : "f"(f))

__device__ __forceinline__ void mma_tf32(float* d, const unsigned* a, const unsigned* b) {
    asm volatile("mma.sync.aligned.m16n8k8.row.col.f32.tf32.tf32.f32 "
        "{%0,%1,%2,%3}, {%4,%5,%6,%7}, {%8,%9}, {%0,%1,%2,%3};"
        : "+f"(d[0]), "+f"(d[1]), "+f"(d[2]), "+f"(d[3])
        : "r"(a[0]), "r"(a[1]), "r"(a[2]), "r"(a[3]), "r"(b[0]), "r"(b[1]));
}

// smem layout (floats):
//  xs   [0      .. 12936)  : x tile 98 x (stride 132); later reused as S (stride 100)
//  q_s  [12936  .. 25480)  : 4 x 98 x 32, swizzled d' = (d+4i)&31  (later O)
//  kT_s [25480  .. 38152)  : 4 x 32 x 99 (k transposed, linear)
//  v_s  [38152  .. 50696)  : 4 x 98 x 32, swizzled
//  wt   [50696  .. 56968)  : 16 x 392 (qkv W chunk) / 16 x 136 (proj W chunk)
#define XS_OFF 0
#define Q_OFF  12936
#define KT_OFF 25480
#define V_OFF  38152
#define WT_OFF 50696
#define SMEM_FLOATS 56968

// precomputed rel-pos bias table: bias[h][i][j]
__device__ float g_bias[HEADS * N_TOK * N_TOK];

__global__ void bias_precompute_kernel(const float* __restrict__ pe)
{
    int idx = blockIdx.x * blockDim.x + threadIdx.x;
    if (idx >= HEADS * N_TOK * N_TOK) return;
    int h = idx / (N_TOK * N_TOK);
    int r = idx % (N_TOK * N_TOK);
    int i = r / N_TOK, j = r % N_TOK;
    int ti = i / 49, rem = i % 49, hi = rem / 7, wi = rem % 7;
    int tj = j / 49, remj = j % 49, hj = remj / 7, wj = remj % 7;
    int ridx = (ti - tj + 1) * 169 + (hi - hj + 6) * 13 + (wi - wj + 6);
    g_bias[idx] = pe[h * 507 + ridx];
}

__global__ __launch_bounds__(THREADS, 1)
void win_attn_kernel(const float* __restrict__ x,
                     const float* __restrict__ mask,
                     const float* __restrict__ qkv_w,
                     const float* __restrict__ qkv_b,
                     const float* __restrict__ proj_w,
                     const float* __restrict__ proj_b,
                     float* __restrict__ out)
{
    extern __shared__ float sm[];
    float* xs   = sm + XS_OFF;
    float* q_s  = sm + Q_OFF;
    float* kT_s = sm + KT_OFF;
    float* v_s  = sm + V_OFF;
    float* wt   = sm + WT_OFF;

    const int b   = blockIdx.x;
    const int tid = threadIdx.x;
    const int tx  = tid & 31;
    const int ty  = tid >> 5;            // warp id 0..15
    const int gid = tx >> 2;             // 0..7 (mma group)
    const int tig = tx & 3;              // 0..3 (mma thread-in-group)
    const float scale = 0.17677669529663687f;  // 32^-0.5

    // ---------------- load x tile (stride 132) ----------------
    {
        const float4* xg4 = (const float4*)(x + (size_t)b * (N_TOK * CDIM));
        for (int idx = tid; idx < N_TOK * 32; idx += THREADS) {
            int i = idx >> 5, j = idx & 31;
            ((float4*)(xs + i * 132))[j] = xg4[i * 32 + j];
        }
    }

    // ---------------- QKV GEMM via tf32 mma: C[98x384] = X @ W^T ----------------
    // warp ty owns N-cols [24*ty, 24*ty+24) as 3 n-tiles; all 7 m-tiles (112 rows).
    {
        float facc[7][3][4];
        #pragma unroll
        for (int mt = 0; mt < 7; ++mt)
            #pragma unroll
            for (int nt = 0; nt < 3; ++nt)
                #pragma unroll
                for (int e = 0; e < 4; ++e) facc[mt][nt][e] = 0.f;

        const int cb = ty * 24;
        for (int ch = 0; ch < 8; ++ch) {       // K chunks of 16
            __syncthreads();
            for (int idx = tid; idx < 16 * 384; idx += THREADS) {
                int kk = idx & 15, cc = idx >> 4;
                wt[kk * 392 + cc] = qkv_w[cc * 128 + ch * 16 + kk];
            }
            __syncthreads();

            #pragma unroll
            for (int ks = 0; ks < 2; ++ks) {   // 2 k8-steps per chunk
                int koff = ks * 8;
                unsigned bfr[3][2];
                #pragma unroll
                for (int nt = 0; nt < 3; ++nt) {
                    CVT_TF32(bfr[nt][0], wt[(koff + tig) * 392 + cb + nt * 8 + gid]);
                    CVT_TF32(bfr[nt][1], wt[(koff + tig + 4) * 392 + cb + nt * 8 + gid]);
                }
                #pragma unroll
                for (int mt = 0; mt < 7; ++mt) {
                    const float* a0p = xs + (mt * 16 + gid) * 132 + ch * 16 + koff + tig;
                    const float* a1p = a0p + 8 * 132;
                    unsigned afr[4];
                    CVT_TF32(afr[0], a0p[0]);
                    CVT_TF32(afr[1], a1p[0]);
                    CVT_TF32(afr[2], a0p[4]);
                    CVT_TF32(afr[3], a1p[4]);
                    #pragma unroll
                    for (int nt = 0; nt < 3; ++nt)
                        mma_tf32(facc[mt][nt], afr, bfr[nt]);
                }
            }
        }

        // epilogue: scatter to q/kT/v
        #pragma unroll
        for (int nt = 0; nt < 3; ++nt) {
            int c0 = cb + nt * 8 + 2 * tig;    // even; (c0,c0+1) same 32-block
            int sect = c0 >> 7;
            int hh   = (c0 >> 5) & 3;
            int d0   = c0 & 31;
            float bi0 = qkv_b[c0], bi1 = qkv_b[c0 + 1];
            #pragma unroll
            for (int mt = 0; mt < 7; ++mt) {
                #pragma unroll
                for (int half = 0; half < 2; ++half) {
                    int i = mt * 16 + gid + half * 8;
                    if (i >= 98) continue;
                    float v0 = facc[mt][nt][half * 2 + 0] + bi0;
                    float v1 = facc[mt][nt][half * 2 + 1] + bi1;
                    if (sect == 0) {
                        q_s[hh * 3136 + i * 32 + ((d0 + 4 * i) & 31)]     = v0 * scale;
                        q_s[hh * 3136 + i * 32 + ((d0 + 1 + 4 * i) & 31)] = v1 * scale;
                    } else if (sect == 1) {
                        kT_s[hh * 3168 + d0 * 99 + i]       = v0;
                        kT_s[hh * 3168 + (d0 + 1) * 99 + i] = v1;
                    } else {
                        v_s[hh * 3136 + i * 32 + ((d0 + 4 * i) & 31)]     = v0;
                        v_s[hh * 3136 + i * 32 + ((d0 + 1 + 4 * i) & 31)] = v1;
                    }
                }
            }
        }
    }
    __syncthreads();   // q/kT/v visible to all warps; xs free for reuse as S

    // ---------------- attention: head loop, NO barriers inside ----------------
    // S rows i = ty + 16r are warp-private end-to-end.
    const float* maskp = mask + (size_t)(b & (LWIN - 1)) * (N_TOK * N_TOK);
    float* S = xs;  // stride 100

    for (int h = 0; h < HEADS; ++h) {
        const float* qh  = q_s  + h * 3136;
        const float* kTh = kT_s + h * 3168;
        const float* vh  = v_s  + h * 3136;
        const float* bh  = g_bias + h * (N_TOK * N_TOK);

        // ---- S = q k^T + bias + mask ----
        {
            unsigned long long acc2[7][2];
            #pragma unroll
            for (int r = 0; r < 7; ++r) { acc2[r][0] = 0ull; acc2[r][1] = 0ull; }

            #pragma unroll
            for (int d4 = 0; d4 < 8; ++d4) {
                float4 qv[7];                  // broadcast loads (swizzle-rotated rows)
                #pragma unroll
                for (int r = 0; r < 7; ++r) {
                    int i = ty + 16 * r; i = i < 98 ? i : 97;
                    qv[r] = *(const float4*)(qh + i * 32 + ((4 * d4 + 4 * i) & 31));
                }
                #pragma unroll
                for (int u = 0; u < 4; ++u) {
                    int d = d4 * 4 + u;
                    int j3 = tx + 96; j3 = j3 < 98 ? j3 : 97;
                    float kv0 = kTh[d * 99 + tx];
                    float kv1 = kTh[d * 99 + tx + 32];
                    float kv2 = kTh[d * 99 + tx + 64];
                    float kv3 = kTh[d * 99 + j3];
                    unsigned long long kvA, kvB;
                    PACK2(kvA, kv0, kv1);
                    PACK2(kvB, kv2, kv3);
                    #pragma unroll
                    for (int r = 0; r < 7; ++r) {
                        float qc = (u == 0) ? qv[r].x : (u == 1) ? qv[r].y
                                 : (u == 2) ? qv[r].z : qv[r].w;
                        unsigned long long qd;
                        PACK2(qd, qc, qc);
                        FMA2(acc2[r][0], qd, kvA, acc2[r][0]);
                        FMA2(acc2[r][1], qd, kvB, acc2[r][1]);
                    }
                }
            }

            #pragma unroll
            for (int r = 0; r < 7; ++r) {
                int i = ty + 16 * r;
                if (i >= 98) continue;
                const float* mrow = maskp + i * 98;
                const float* brow = bh + i * 98;
                float* srow = S + i * 100;
                float s0, s1, s2, s3;
                UNPACK2(s0, s1, acc2[r][0]);
                UNPACK2(s2, s3, acc2[r][1]);
                srow[tx]      = s0 + brow[tx]      + mrow[tx];
                srow[tx + 32] = s1 + brow[tx + 32] + mrow[tx + 32];
                srow[tx + 64] = s2 + brow[tx + 64] + mrow[tx + 64];
                if (tx < 2)
                    srow[tx + 96] = s3 + brow[tx + 96] + mrow[tx + 96];
            }
        }

        // ---- softmax (warp-private rows) ----
        #pragma unroll
        for (int r = 0; r < 7; ++r) {
            int i = ty + 16 * r;
            if (i >= 98) continue;
            float vals[4]; float m = -1e30f;
            #pragma unroll
            for (int jt = 0; jt < 4; ++jt) {
                int j = tx + 32 * jt;
                vals[jt] = (j < 98) ? S[i * 100 + j] : -1e30f;
                m = fmaxf(m, vals[jt]);
            }
            #pragma unroll
            for (int o = 16; o > 0; o >>= 1) m = fmaxf(m, __shfl_xor_sync(0xffffffffu, m, o));
            float ssum = 0.f;
            #pragma unroll
            for (int jt = 0; jt < 4; ++jt) {
                int j = tx + 32 * jt;
                float p = (j < 98) ? __expf(vals[jt] - m) : 0.f;
                vals[jt] = p; ssum += p;
            }
            #pragma unroll
            for (int o = 16; o > 0; o >>= 1) ssum += __shfl_xor_sync(0xffffffffu, ssum, o);
            float inv = 1.f / ssum;
            #pragma unroll
            for (int jt = 0; jt < 4; ++jt) {
                int j = tx + 32 * jt;
                if (j < 98) S[i * 100 + j] = vals[jt] * inv;
            }
        }

        // ---- O = P @ V (packed even/odd-j, reduced at end) ----
        unsigned long long oacc2[7];
        #pragma unroll
        for (int r = 0; r < 7; ++r) oacc2[r] = 0ull;

        for (int t = 0; t < 6; ++t) {
            int j0 = t * 16;
            unsigned long long vpk[8];
            #pragma unroll
            for (int u = 0; u < 8; ++u) {
                int j = j0 + 2 * u;
                float v0 = vh[j * 32       + ((tx + 4 * j) & 31)];
                float v1 = vh[(j + 1) * 32 + ((tx + 4 * (j + 1)) & 31)];
                PACK2(vpk[u], v0, v1);
            }
            #pragma unroll
            for (int r = 0; r < 7; ++r) {
                int i = ty + 16 * r; i = i < 98 ? i : 97;
                const ulonglong2* p2 = (const ulonglong2*)(S + i * 100 + j0);
                #pragma unroll
                for (int q4 = 0; q4 < 4; ++q4) {
                    ulonglong2 pp = p2[q4];
                    FMA2(oacc2[r], pp.x, vpk[2 * q4],     oacc2[r]);
                    FMA2(oacc2[r], pp.y, vpk[2 * q4 + 1], oacc2[r]);
                }
            }
        }
        {   // tail j = 96, 97; (4*96)&31 == 0, (4*97)&31 == 4
            float v0 = vh[96 * 32 + (tx & 31)];
            float v1 = vh[97 * 32 + ((tx + 4) & 31)];
            unsigned long long vt;
            PACK2(vt, v0, v1);
            #pragma unroll
            for (int r = 0; r < 7; ++r) {
                int i = ty + 16 * r; i = i < 98 ? i : 97;
                unsigned long long pt = *(const unsigned long long*)(S + i * 100 + 96);
                FMA2(oacc2[r], pt, vt, oacc2[r]);
            }
        }
        #pragma unroll
        for (int r = 0; r < 7; ++r) {
            int i = ty + 16 * r;
            if (i >= 98) continue;
            float lo, hi;
            UNPACK2(lo, hi, oacc2[r]);
            q_s[h * 3136 + i * 32 + ((tx + 4 * i) & 31)] = lo + hi;   // O, swizzled
        }
    }

    // ---------------- projection via tf32 mma: out = O @ Wp^T + b ----------------
    // warp ty owns cols [8*ty, 8*ty+8); O read from swizzled q_s.
    {
        float facc[7][4];
        #pragma unroll
        for (int mt = 0; mt < 7; ++mt)
            #pragma unroll
            for (int e = 0; e < 4; ++e) facc[mt][e] = 0.f;

        const int cb = ty * 8;
        for (int ch = 0; ch < 8; ++ch) {
            __syncthreads();   // covers O writes (first iter) / prior wt use
            for (int idx = tid; idx < 16 * 128; idx += THREADS) {
                int kk = idx & 15, cc = idx >> 4;
                wt[kk * 136 + cc] = proj_w[cc * 128 + ch * 16 + kk];
            }
            __syncthreads();

            #pragma unroll
            for (int ks = 0; ks < 2; ++ks) {
                int koff = ks * 8;
                unsigned bfr[2];
                CVT_TF32(bfr[0], wt[(koff + tig) * 136 + cb + gid]);
                CVT_TF32(bfr[1], wt[(koff + tig + 4) * 136 + cb + gid]);
                int kglob = ch * 16 + koff;     // multiple of 8
                int kh = kglob >> 5;
                int cb_k = (kglob & 31) + tig;  // <= 27; +4 stays in block
                const float* Oh = q_s + kh * 3136;
                #pragma unroll
                for (int mt = 0; mt < 7; ++mt) {
                    int i0 = mt * 16 + gid;     int i0c = i0 < 98 ? i0 : 97;
                    int i1 = i0 + 8;            int i1c = i1 < 98 ? i1 : 97;
                    unsigned afr[4];
                    CVT_TF32(afr[0], Oh[i0c * 32 + ((cb_k + 4 * i0c) & 31)]);
                    CVT_TF32(afr[1], Oh[i1c * 32 + ((cb_k + 4 * i1c) & 31)]);
                    CVT_TF32(afr[2], Oh[i0c * 32 + ((cb_k + 4 + 4 * i0c) & 31)]);
                    CVT_TF32(afr[3], Oh[i1c * 32 + ((cb_k + 4 + 4 * i1c) & 31)]);
                    mma_tf32(facc[mt], afr, bfr);
                }
            }
        }

        float pb0 = proj_b[cb + 2 * tig];
        float pb1 = proj_b[cb + 2 * tig + 1];
        float* outb = out + (size_t)b * (N_TOK * CDIM);
        #pragma unroll
        for (int mt = 0; mt < 7; ++mt) {
            #pragma unroll
            for (int half = 0; half < 2; ++half) {
                int i = mt * 16 + gid + half * 8;
                if (i >= 98) continue;
                float2 v;
                v.x = facc[mt][half * 2 + 0] + pb0;
                v.y = facc[mt][half * 2 + 1] + pb1;
                *(float2*)(outb + i * 128 + cb + 2 * tig) = v;
            }
        }
    }
}

extern "C" void kernel_launch(void* const* d_in, const int* in_sizes, int n_in,
                              void* d_out, int out_size)
{
    const float* x      = (const float*)d_in[0];
    const float* mask   = (const float*)d_in[1];
    const float* qkv_w  = (const float*)d_in[2];
    const float* qkv_b  = (const float*)d_in[3];
    const float* pe     = (const float*)d_in[4];
    const float* proj_w = (const float*)d_in[5];
    const float* proj_b = (const float*)d_in[6];
    float* out = (float*)d_out;

    bias_precompute_kernel<<<(HEADS * N_TOK * N_TOK + 255) / 256, 256>>>(pe);

    const int smem_bytes = SMEM_FLOATS * sizeof(float);   // 227872
    cudaFuncSetAttribute(win_attn_kernel,
                         cudaFuncAttributeMaxDynamicSharedMemorySize, smem_bytes);

    int nwin = in_sizes[0] / (N_TOK * CDIM);              // 2048
    win_attn_kernel<<<nwin, THREADS, smem_bytes>>>(
        x, mask, qkv_w, qkv_b, proj_w, proj_b, out);
}

// round 9
// speedup vs baseline: 2.6208x; 1.2710x over previous
#include <cuda_runtime.h>

#define THREADS 512          // 16 warps
#define N_TOK 98
#define CDIM 128
#define HEADS 4
#define LWIN 512

#define CVT_TF32(u, f) asm("cvt.rna.tf32.f32 %0, %1;" : "=r"(u) : "f"(f))

__device__ __forceinline__ void mma_tf32(float* d, const unsigned* a, const unsigned* b) {
    asm volatile("mma.sync.aligned.m16n8k8.row.col.f32.tf32.tf32.f32 "
        "{%0,%1,%2,%3}, {%4,%5,%6,%7}, {%8,%9}, {%0,%1,%2,%3};"
        : "+f"(d[0]), "+f"(d[1]), "+f"(d[2]), "+f"(d[3])
        : "r"(a[0]), "r"(a[1]), "r"(a[2]), "r"(a[3]), "r"(b[0]), "r"(b[1]));
}

// smem layout (floats):
//  xs  [0     .. 12544) : x tile 98x128, swizzle col' = (c+4i)&127; later O (same swizzle)
//  q_s [12544 .. 25088) : 4 x 98 x 32, tf32 bits, swizzle d' = (d+4i)&31
//  kT  [25088 .. 38400) : 4 x 32 x 104 (k transposed [d][j], tf32 bits)
//  vT  [38400 .. 51712) : 4 x 32 x 104 (v transposed [d][j], tf32 bits; j pad 98..103 zeroed)
//  wt  [51712 .. 57984) : 16 x 392 (qkv W chunk) / 16 x 136 (proj W chunk)
#define XS_OFF 0
#define Q_OFF  12544
#define KT_OFF 25088
#define VT_OFF 38400
#define WT_OFF 51712
#define SMEM_FLOATS 57984

// precomputed rel-pos bias table: bias[h][i][j]
__device__ float g_bias[HEADS * N_TOK * N_TOK];

__global__ void bias_precompute_kernel(const float* __restrict__ pe)
{
    int idx = blockIdx.x * blockDim.x + threadIdx.x;
    if (idx >= HEADS * N_TOK * N_TOK) return;
    int h = idx / (N_TOK * N_TOK);
    int r = idx % (N_TOK * N_TOK);
    int i = r / N_TOK, j = r % N_TOK;
    int ti = i / 49, rem = i % 49, hi = rem / 7, wi = rem % 7;
    int tj = j / 49, remj = j % 49, hj = remj / 7, wj = remj % 7;
    int ridx = (ti - tj + 1) * 169 + (hi - hj + 6) * 13 + (wi - wj + 6);
    g_bias[idx] = pe[h * 507 + ridx];
}

__global__ __launch_bounds__(THREADS, 1)
void win_attn_kernel(const float* __restrict__ x,
                     const float* __restrict__ mask,
                     const float* __restrict__ qkv_w,
                     const float* __restrict__ qkv_b,
                     const float* __restrict__ proj_w,
                     const float* __restrict__ proj_b,
                     float* __restrict__ out)
{
    extern __shared__ float sm[];
    float* xs  = sm + XS_OFF;
    float* q_s = sm + Q_OFF;
    float* kT  = sm + KT_OFF;
    float* vT  = sm + VT_OFF;
    float* wt  = sm + WT_OFF;

    const int b   = blockIdx.x;
    const int tid = threadIdx.x;
    const int tx  = tid & 31;
    const int ty  = tid >> 5;            // warp id 0..15
    const int gid = tx >> 2;             // 0..7 (mma group)
    const int tig = tx & 3;              // 0..3 (thread-in-group)
    const float scale = 0.17677669529663687f;  // 32^-0.5

    // ---------------- load x tile (swizzled) + zero vT padding ----------------
    {
        const float4* xg4 = (const float4*)(x + (size_t)b * (N_TOK * CDIM));
        for (int idx = tid; idx < N_TOK * 32; idx += THREADS) {
            int i = idx >> 5, j4 = idx & 31;
            int sw = ((j4 * 4 + 4 * i) & 127) >> 2;
            ((float4*)xs)[i * 32 + sw] = xg4[i * 32 + j4];
        }
        for (int idx = tid; idx < HEADS * 32 * 6; idx += THREADS) {
            int h = idx / 192, rem = idx % 192, d = rem / 6, e = rem % 6;
            vT[h * 3328 + d * 104 + 98 + e] = 0.f;
        }
    }

    // ---------------- QKV GEMM via tf32 mma: C[98x384] = X @ W^T ----------------
    {
        float facc[7][3][4];
        #pragma unroll
        for (int mt = 0; mt < 7; ++mt)
            #pragma unroll
            for (int nt = 0; nt < 3; ++nt)
                #pragma unroll
                for (int e = 0; e < 4; ++e) facc[mt][nt][e] = 0.f;

        const int cb = ty * 24;
        for (int ch = 0; ch < 8; ++ch) {       // K chunks of 16
            __syncthreads();
            for (int idx = tid; idx < 16 * 384; idx += THREADS) {
                int kk = idx & 15, cc = idx >> 4;
                wt[kk * 392 + cc] = qkv_w[cc * 128 + ch * 16 + kk];
            }
            __syncthreads();

            #pragma unroll
            for (int ks = 0; ks < 2; ++ks) {
                int koff = ks * 8;
                unsigned bfr[3][2];
                #pragma unroll
                for (int nt = 0; nt < 3; ++nt) {
                    CVT_TF32(bfr[nt][0], wt[(koff + tig) * 392 + cb + nt * 8 + gid]);
                    CVT_TF32(bfr[nt][1], wt[(koff + tig + 4) * 392 + cb + nt * 8 + gid]);
                }
                #pragma unroll
                for (int mt = 0; mt < 7; ++mt) {
                    int i0 = mt * 16 + gid, i1 = i0 + 8;
                    int c = ch * 16 + koff + tig;
                    unsigned afr[4];
                    CVT_TF32(afr[0], xs[i0 * 128 + ((c + 4 * i0) & 127)]);
                    CVT_TF32(afr[1], xs[i1 * 128 + ((c + 4 * i1) & 127)]);
                    CVT_TF32(afr[2], xs[i0 * 128 + ((c + 4 + 4 * i0) & 127)]);
                    CVT_TF32(afr[3], xs[i1 * 128 + ((c + 4 + 4 * i1) & 127)]);
                    #pragma unroll
                    for (int nt = 0; nt < 3; ++nt)
                        mma_tf32(facc[mt][nt], afr, bfr[nt]);
                }
            }
        }

        // epilogue: bias add, convert to tf32 bits, scatter to q/kT/vT
        #pragma unroll
        for (int nt = 0; nt < 3; ++nt) {
            int c0 = cb + nt * 8 + 2 * tig;    // even; (c0,c0+1) same 32-block
            int sect = c0 >> 7;
            int hh   = (c0 >> 5) & 3;
            int d0   = c0 & 31;
            float bi0 = qkv_b[c0], bi1 = qkv_b[c0 + 1];
            #pragma unroll
            for (int mt = 0; mt < 7; ++mt) {
                #pragma unroll
                for (int half = 0; half < 2; ++half) {
                    int i = mt * 16 + gid + half * 8;
                    if (i >= 98) continue;
                    float v0 = facc[mt][nt][half * 2 + 0] + bi0;
                    float v1 = facc[mt][nt][half * 2 + 1] + bi1;
                    unsigned u0, u1;
                    if (sect == 0) {
                        CVT_TF32(u0, v0 * scale);
                        CVT_TF32(u1, v1 * scale);
                        q_s[hh * 3136 + i * 32 + ((d0 + 4 * i) & 31)]     = __uint_as_float(u0);
                        q_s[hh * 3136 + i * 32 + ((d0 + 1 + 4 * i) & 31)] = __uint_as_float(u1);
                    } else if (sect == 1) {
                        CVT_TF32(u0, v0);
                        CVT_TF32(u1, v1);
                        kT[hh * 3328 + d0 * 104 + i]       = __uint_as_float(u0);
                        kT[hh * 3328 + (d0 + 1) * 104 + i] = __uint_as_float(u1);
                    } else {
                        CVT_TF32(u0, v0);
                        CVT_TF32(u1, v1);
                        vT[hh * 3328 + d0 * 104 + i]       = __uint_as_float(u0);
                        vT[hh * 3328 + (d0 + 1) * 104 + i] = __uint_as_float(u1);
                    }
                }
            }
        }
    }
    __syncthreads();   // q/kT/vT visible; xs free for reuse as O

    // ---------------- attention: 28 warp-tasks (head, m-tile), NO barriers ----------------
    const float* maskp = mask + (size_t)(b & (LWIN - 1)) * (N_TOK * N_TOK);
    const int qsrc0 = (tx & ~3) | (tig >> 1);
    const int qsrc1 = qsrc0 | 2;
    const bool odd = tig & 1;

    for (int task = ty; task < 28; task += 16) {
        int h = task & 3, mt = task >> 2;
        int i0 = mt * 16 + gid, i1 = i0 + 8;
        bool val0 = i0 < 98, val1 = i1 < 98;
        const float* qh = q_s + h * 3136;
        const float* kh = kT + h * 3328;
        const float* vh = vT + h * 3328;

        // ---- S = q k^T (tf32 mma), C-frags in registers ----
        float s[13][4];
        #pragma unroll
        for (int nt = 0; nt < 13; ++nt)
            #pragma unroll
            for (int e = 0; e < 4; ++e) s[nt][e] = 0.f;

        #pragma unroll
        for (int ks = 0; ks < 4; ++ks) {
            int d = ks * 8 + tig;
            unsigned a[4];
            a[0] = __float_as_uint(qh[i0 * 32 + ((d + 4 * i0) & 31)]);
            a[1] = __float_as_uint(qh[i1 * 32 + ((d + 4 * i1) & 31)]);
            a[2] = __float_as_uint(qh[i0 * 32 + ((d + 4 + 4 * i0) & 31)]);
            a[3] = __float_as_uint(qh[i1 * 32 + ((d + 4 + 4 * i1) & 31)]);
            #pragma unroll
            for (int nt = 0; nt < 13; ++nt) {
                unsigned bb[2];
                bb[0] = __float_as_uint(kh[d * 104 + nt * 8 + gid]);
                bb[1] = __float_as_uint(kh[(d + 4) * 104 + nt * 8 + gid]);
                mma_tf32(s[nt], a, bb);
            }
        }

        // ---- bias + mask + softmax on fragments ----
        const float* bh = g_bias + h * (N_TOK * N_TOK);
        float m0 = -1e30f, m1 = -1e30f;
        #pragma unroll
        for (int nt = 0; nt < 13; ++nt) {
            int j0 = nt * 8 + 2 * tig;
            if (j0 < 98) {   // j0 even -> j0+1 <= 97
                if (val0) {
                    float2 bb = *(const float2*)(bh + i0 * 98 + j0);
                    float2 mm = *(const float2*)(maskp + i0 * 98 + j0);
                    s[nt][0] += bb.x + mm.x;
                    s[nt][1] += bb.y + mm.y;
                }
                if (val1) {
                    float2 bb = *(const float2*)(bh + i1 * 98 + j0);
                    float2 mm = *(const float2*)(maskp + i1 * 98 + j0);
                    s[nt][2] += bb.x + mm.x;
                    s[nt][3] += bb.y + mm.y;
                }
            } else {
                s[nt][0] = s[nt][1] = s[nt][2] = s[nt][3] = -1e30f;
            }
            m0 = fmaxf(m0, fmaxf(s[nt][0], s[nt][1]));
            m1 = fmaxf(m1, fmaxf(s[nt][2], s[nt][3]));
        }
        m0 = fmaxf(m0, __shfl_xor_sync(0xffffffffu, m0, 1));
        m0 = fmaxf(m0, __shfl_xor_sync(0xffffffffu, m0, 2));
        m1 = fmaxf(m1, __shfl_xor_sync(0xffffffffu, m1, 1));
        m1 = fmaxf(m1, __shfl_xor_sync(0xffffffffu, m1, 2));

        float z0 = 0.f, z1 = 0.f;
        #pragma unroll
        for (int nt = 0; nt < 13; ++nt) {
            s[nt][0] = __expf(s[nt][0] - m0);
            s[nt][1] = __expf(s[nt][1] - m0);
            s[nt][2] = __expf(s[nt][2] - m1);
            s[nt][3] = __expf(s[nt][3] - m1);
            z0 += s[nt][0] + s[nt][1];
            z1 += s[nt][2] + s[nt][3];
        }
        z0 += __shfl_xor_sync(0xffffffffu, z0, 1);
        z0 += __shfl_xor_sync(0xffffffffu, z0, 2);
        z1 += __shfl_xor_sync(0xffffffffu, z1, 1);
        z1 += __shfl_xor_sync(0xffffffffu, z1, 2);
        float inv0 = 1.f / z0, inv1 = 1.f / z1;

        // ---- O = P @ V (tf32 mma); P C-frags -> A-frags via quad shuffles ----
        float o[4][4];
        #pragma unroll
        for (int nt = 0; nt < 4; ++nt)
            #pragma unroll
            for (int e = 0; e < 4; ++e) o[nt][e] = 0.f;

        #pragma unroll
        for (int jt = 0; jt < 13; ++jt) {
            float t00 = __shfl_sync(0xffffffffu, s[jt][0], qsrc0);
            float t01 = __shfl_sync(0xffffffffu, s[jt][1], qsrc0);
            float t10 = __shfl_sync(0xffffffffu, s[jt][2], qsrc0);
            float t11 = __shfl_sync(0xffffffffu, s[jt][3], qsrc0);
            float t20 = __shfl_sync(0xffffffffu, s[jt][0], qsrc1);
            float t21 = __shfl_sync(0xffffffffu, s[jt][1], qsrc1);
            float t30 = __shfl_sync(0xffffffffu, s[jt][2], qsrc1);
            float t31 = __shfl_sync(0xffffffffu, s[jt][3], qsrc1);
            unsigned pa[4];
            CVT_TF32(pa[0], odd ? t01 : t00);   // P[gid][8jt+tig]
            CVT_TF32(pa[1], odd ? t11 : t10);   // P[gid+8][8jt+tig]
            CVT_TF32(pa[2], odd ? t21 : t20);   // P[gid][8jt+tig+4]
            CVT_TF32(pa[3], odd ? t31 : t30);   // P[gid+8][8jt+tig+4]
            #pragma unroll
            for (int nt = 0; nt < 4; ++nt) {
                unsigned bb[2];
                bb[0] = __float_as_uint(vh[(nt * 8 + gid) * 104 + jt * 8 + tig]);
                bb[1] = __float_as_uint(vh[(nt * 8 + gid) * 104 + jt * 8 + tig + 4]);
                mma_tf32(o[nt], pa, bb);
            }
        }

        // ---- store O (normalized) into xs, swizzle col' = (C+4i)&127 ----
        #pragma unroll
        for (int nt = 0; nt < 4; ++nt) {
            int C = h * 32 + nt * 8 + 2 * tig;
            if (val0) {
                float2 w2; w2.x = o[nt][0] * inv0; w2.y = o[nt][1] * inv0;
                *(float2*)(xs + i0 * 128 + ((C + 4 * i0) & 127)) = w2;
            }
            if (val1) {
                float2 w2; w2.x = o[nt][2] * inv1; w2.y = o[nt][3] * inv1;
                *(float2*)(xs + i1 * 128 + ((C + 4 * i1) & 127)) = w2;
            }
        }
    }
    __syncthreads();   // all O written before proj

    // ---------------- projection via tf32 mma: out = O @ Wp^T + b ----------------
    {
        float facc[7][4];
        #pragma unroll
        for (int mt = 0; mt < 7; ++mt)
            #pragma unroll
            for (int e = 0; e < 4; ++e) facc[mt][e] = 0.f;

        const int cb = ty * 8;
        for (int ch = 0; ch < 8; ++ch) {
            for (int idx = tid; idx < 16 * 128; idx += THREADS) {
                int kk = idx & 15, cc = idx >> 4;
                wt[kk * 136 + cc] = proj_w[cc * 128 + ch * 16 + kk];
            }
            __syncthreads();

            #pragma unroll
            for (int ks = 0; ks < 2; ++ks) {
                int koff = ks * 8;
                unsigned bfr[2];
                CVT_TF32(bfr[0], wt[(koff + tig) * 136 + cb + gid]);
                CVT_TF32(bfr[1], wt[(koff + tig + 4) * 136 + cb + gid]);
                #pragma unroll
                for (int mt = 0; mt < 7; ++mt) {
                    int i0 = mt * 16 + gid, i1 = i0 + 8;
                    int c = ch * 16 + koff + tig;
                    unsigned afr[4];
                    CVT_TF32(afr[0], xs[i0 * 128 + ((c + 4 * i0) & 127)]);
                    CVT_TF32(afr[1], xs[i1 * 128 + ((c + 4 * i1) & 127)]);
                    CVT_TF32(afr[2], xs[i0 * 128 + ((c + 4 + 4 * i0) & 127)]);
                    CVT_TF32(afr[3], xs[i1 * 128 + ((c + 4 + 4 * i1) & 127)]);
                    mma_tf32(facc[mt], afr, bfr);
                }
            }
            __syncthreads();   // wt reuse safety
        }

        float pb0 = proj_b[cb + 2 * tig];
        float pb1 = proj_b[cb + 2 * tig + 1];
        float* outb = out + (size_t)b * (N_TOK * CDIM);
        #pragma unroll
        for (int mt = 0; mt < 7; ++mt) {
            #pragma unroll
            for (int half = 0; half < 2; ++half) {
                int i = mt * 16 + gid + half * 8;
                if (i >= 98) continue;
                float2 v;
                v.x = facc[mt][half * 2 + 0] + pb0;
                v.y = facc[mt][half * 2 + 1] + pb1;
                *(float2*)(outb + i * 128 + cb + 2 * tig) = v;
            }
        }
    }
}

extern "C" void kernel_launch(void* const* d_in, const int* in_sizes, int n_in,
                              void* d_out, int out_size)
{
    const float* x      = (const float*)d_in[0];
    const float* mask   = (const float*)d_in[1];
    const float* qkv_w  = (const float*)d_in[2];
    const float* qkv_b  = (const float*)d_in[3];
    const float* pe     = (const float*)d_in[4];
    const float* proj_w = (const float*)d_in[5];
    const float* proj_b = (const float*)d_in[6];
    float* out = (float*)d_out;

    bias_precompute_kernel<<<(HEADS * N_TOK * N_TOK + 255) / 256, 256>>>(pe);

    const int smem_bytes = SMEM_FLOATS * sizeof(float);   // 231936
    cudaFuncSetAttribute(win_attn_kernel,
                         cudaFuncAttributeMaxDynamicSharedMemorySize, smem_bytes);

    int nwin = in_sizes[0] / (N_TOK * CDIM);              // 2048
    win_attn_kernel<<<nwin, THREADS, smem_bytes>>>(
        x, mask, qkv_w, qkv_b, proj_w, proj_b, out);
}

// round 10
// speedup vs baseline: 3.0466x; 1.1625x over previous
#include <cuda_runtime.h>

#define THREADS 512          // 16 warps
#define N_TOK 98
#define CDIM 128
#define HEADS 4
#define LWIN 512

#define CVT_TF32(u, f) asm("cvt.rna.tf32.f32 %0, %1;" : "=r"(u) : "f"(f))

__device__ __forceinline__ void mma_tf32(float* d, const unsigned* a, const unsigned* b) {
    asm volatile("mma.sync.aligned.m16n8k8.row.col.f32.tf32.tf32.f32 "
        "{%0,%1,%2,%3}, {%4,%5,%6,%7}, {%8,%9}, {%0,%1,%2,%3};"
        : "+f"(d[0]), "+f"(d[1]), "+f"(d[2]), "+f"(d[3])
        : "r"(a[0]), "r"(a[1]), "r"(a[2]), "r"(a[3]), "r"(b[0]), "r"(b[1]));
}

// smem layout (floats; tf32 operands stored as raw bit patterns):
//  xs  [0     .. 12544) : x tile 98x128 tf32 bits, swizzle col' = (c+4i)&127; later O bits
//  q_s [12544 .. 25088) : 4 x 98 x 32, tf32 bits, swizzle d' = (d+4i)&31
//  kT  [25088 .. 38400) : 4 x 32 x 104 (k transposed [d][j], tf32 bits; j pad zeroed)
//  vT  [38400 .. 51712) : 4 x 32 x 104 (v transposed [d][j], tf32 bits; j pad zeroed)
//  wt  [51712 .. 57984) : 16 x 392 (qkv W chunk, tf32 bits) / 16 x 136 (proj W chunk)
#define XS_OFF 0
#define Q_OFF  12544
#define KT_OFF 25088
#define VT_OFF 38400
#define WT_OFF 51712
#define SMEM_FLOATS 57984

// precomputed rel-pos bias table: bias[h][i][j]
__device__ float g_bias[HEADS * N_TOK * N_TOK];

__global__ void bias_precompute_kernel(const float* __restrict__ pe)
{
    int idx = blockIdx.x * blockDim.x + threadIdx.x;
    if (idx >= HEADS * N_TOK * N_TOK) return;
    int h = idx / (N_TOK * N_TOK);
    int r = idx % (N_TOK * N_TOK);
    int i = r / N_TOK, j = r % N_TOK;
    int ti = i / 49, rem = i % 49, hi = rem / 7, wi = rem % 7;
    int tj = j / 49, remj = j % 49, hj = remj / 7, wj = remj % 7;
    int ridx = (ti - tj + 1) * 169 + (hi - hj + 6) * 13 + (wi - wj + 6);
    g_bias[idx] = pe[h * 507 + ridx];
}

__global__ __launch_bounds__(THREADS, 1)
void win_attn_kernel(const float* __restrict__ x,
                     const float* __restrict__ mask,
                     const float* __restrict__ qkv_w,
                     const float* __restrict__ qkv_b,
                     const float* __restrict__ proj_w,
                     const float* __restrict__ proj_b,
                     float* __restrict__ out)
{
    extern __shared__ float sm[];
    float* xs  = sm + XS_OFF;
    float* q_s = sm + Q_OFF;
    float* kT  = sm + KT_OFF;
    float* vT  = sm + VT_OFF;
    float* wt  = sm + WT_OFF;

    const int b   = blockIdx.x;
    const int tid = threadIdx.x;
    const int tx  = tid & 31;
    const int ty  = tid >> 5;            // warp id 0..15
    const int gid = tx >> 2;             // 0..7 (mma group)
    const int tig = tx & 3;              // 0..3 (thread-in-group)
    const float scale = 0.17677669529663687f;  // 32^-0.5

    // ---------------- load x tile (convert to tf32 bits once) + zero k/v pads ----------------
    {
        const float4* xg4 = (const float4*)(x + (size_t)b * (N_TOK * CDIM));
        for (int idx = tid; idx < N_TOK * 32; idx += THREADS) {
            int i = idx >> 5, j4 = idx & 31;
            float4 v = xg4[i * 32 + j4];
            uint4 u;
            CVT_TF32(u.x, v.x); CVT_TF32(u.y, v.y);
            CVT_TF32(u.z, v.z); CVT_TF32(u.w, v.w);
            int sw = ((j4 * 4 + 4 * i) & 127) >> 2;
            ((uint4*)xs)[i * 32 + sw] = u;
        }
        for (int idx = tid; idx < HEADS * 32 * 6; idx += THREADS) {
            int h = idx / 192, rem = idx % 192, d = rem / 6, e = rem % 6;
            kT[h * 3328 + d * 104 + 98 + e] = 0.f;
            vT[h * 3328 + d * 104 + 98 + e] = 0.f;
        }
    }

    // ---------------- QKV GEMM via tf32 mma: C[98x384] = X @ W^T ----------------
    // Register-prefetched weight chunks; wt holds tf32 bits.
    {
        float facc[7][3][4];
        #pragma unroll
        for (int mt = 0; mt < 7; ++mt)
            #pragma unroll
            for (int nt = 0; nt < 3; ++nt)
                #pragma unroll
                for (int e = 0; e < 4; ++e) facc[mt][nt][e] = 0.f;

        float wreg[12];
        #pragma unroll
        for (int u = 0; u < 12; ++u) {
            int idx = tid + u * THREADS;
            int kk = idx & 15, cc = idx >> 4;
            wreg[u] = qkv_w[cc * 128 + kk];           // chunk 0
        }

        const int cb = ty * 24;
        for (int ch = 0; ch < 8; ++ch) {
            __syncthreads();                           // wt free / x STS done
            #pragma unroll
            for (int u = 0; u < 12; ++u) {
                int idx = tid + u * THREADS;
                int kk = idx & 15, cc = idx >> 4;
                unsigned uu; CVT_TF32(uu, wreg[u]);
                wt[kk * 392 + cc] = __uint_as_float(uu);
            }
            if (ch < 7) {
                #pragma unroll
                for (int u = 0; u < 12; ++u) {
                    int idx = tid + u * THREADS;
                    int kk = idx & 15, cc = idx >> 4;
                    wreg[u] = qkv_w[cc * 128 + (ch + 1) * 16 + kk];
                }
            }
            __syncthreads();

            #pragma unroll
            for (int ks = 0; ks < 2; ++ks) {
                int koff = ks * 8;
                unsigned bfr[3][2];
                #pragma unroll
                for (int nt = 0; nt < 3; ++nt) {
                    bfr[nt][0] = __float_as_uint(wt[(koff + tig) * 392 + cb + nt * 8 + gid]);
                    bfr[nt][1] = __float_as_uint(wt[(koff + tig + 4) * 392 + cb + nt * 8 + gid]);
                }
                #pragma unroll
                for (int mt = 0; mt < 7; ++mt) {
                    int i0 = mt * 16 + gid, i1 = i0 + 8;
                    int c = ch * 16 + koff + tig;
                    unsigned afr[4];
                    afr[0] = __float_as_uint(xs[i0 * 128 + ((c + 4 * i0) & 127)]);
                    afr[1] = __float_as_uint(xs[i1 * 128 + ((c + 4 * i1) & 127)]);
                    afr[2] = __float_as_uint(xs[i0 * 128 + ((c + 4 + 4 * i0) & 127)]);
                    afr[3] = __float_as_uint(xs[i1 * 128 + ((c + 4 + 4 * i1) & 127)]);
                    #pragma unroll
                    for (int nt = 0; nt < 3; ++nt)
                        mma_tf32(facc[mt][nt], afr, bfr[nt]);
                }
            }
        }

        // epilogue: bias add, convert to tf32 bits, scatter to q/kT/vT
        #pragma unroll
        for (int nt = 0; nt < 3; ++nt) {
            int c0 = cb + nt * 8 + 2 * tig;    // even; (c0,c0+1) same 32-block
            int sect = c0 >> 7;
            int hh   = (c0 >> 5) & 3;
            int d0   = c0 & 31;
            float bi0 = qkv_b[c0], bi1 = qkv_b[c0 + 1];
            #pragma unroll
            for (int mt = 0; mt < 7; ++mt) {
                #pragma unroll
                for (int half = 0; half < 2; ++half) {
                    int i = mt * 16 + gid + half * 8;
                    if (i >= 98) continue;
                    float v0 = facc[mt][nt][half * 2 + 0] + bi0;
                    float v1 = facc[mt][nt][half * 2 + 1] + bi1;
                    unsigned u0, u1;
                    if (sect == 0) {
                        CVT_TF32(u0, v0 * scale);
                        CVT_TF32(u1, v1 * scale);
                        q_s[hh * 3136 + i * 32 + ((d0 + 4 * i) & 31)]     = __uint_as_float(u0);
                        q_s[hh * 3136 + i * 32 + ((d0 + 1 + 4 * i) & 31)] = __uint_as_float(u1);
                    } else if (sect == 1) {
                        CVT_TF32(u0, v0);
                        CVT_TF32(u1, v1);
                        kT[hh * 3328 + d0 * 104 + i]       = __uint_as_float(u0);
                        kT[hh * 3328 + (d0 + 1) * 104 + i] = __uint_as_float(u1);
                    } else {
                        CVT_TF32(u0, v0);
                        CVT_TF32(u1, v1);
                        vT[hh * 3328 + d0 * 104 + i]       = __uint_as_float(u0);
                        vT[hh * 3328 + (d0 + 1) * 104 + i] = __uint_as_float(u1);
                    }
                }
            }
        }
    }
    __syncthreads();   // q/kT/vT visible; xs free for reuse as O

    // ---------------- attention: 28 warp-tasks (head, m-tile), NO barriers ----------------
    const float* maskp = mask + (size_t)(b & (LWIN - 1)) * (N_TOK * N_TOK);
    const int qsrc0 = (tx & ~3) | (tig >> 1);
    const int qsrc1 = qsrc0 | 2;
    const bool odd = tig & 1;

    for (int task = ty; task < 28; task += 16) {
        int h = task & 3, mt = task >> 2;
        int i0 = mt * 16 + gid, i1 = i0 + 8;
        bool val0 = i0 < 98, val1 = i1 < 98;
        const float* qh = q_s + h * 3136;
        const float* kh = kT + h * 3328;
        const float* vh = vT + h * 3328;
        const float* bh = g_bias + h * (N_TOK * N_TOK);

        // ---- init S frags with bias + mask (LDGs issue BEFORE mma, latency hidden) ----
        float s[13][4];
        #pragma unroll
        for (int nt = 0; nt < 13; ++nt) {
            int j0 = nt * 8 + 2 * tig;
            if (j0 < 98) {   // j0 even -> j0+1 <= 97
                if (val0) {
                    float2 bb = *(const float2*)(bh + i0 * 98 + j0);
                    float2 mm = *(const float2*)(maskp + i0 * 98 + j0);
                    s[nt][0] = bb.x + mm.x;
                    s[nt][1] = bb.y + mm.y;
                } else { s[nt][0] = s[nt][1] = 0.f; }
                if (val1) {
                    float2 bb = *(const float2*)(bh + i1 * 98 + j0);
                    float2 mm = *(const float2*)(maskp + i1 * 98 + j0);
                    s[nt][2] = bb.x + mm.x;
                    s[nt][3] = bb.y + mm.y;
                } else { s[nt][2] = s[nt][3] = 0.f; }
            } else {
                // kT pad is zeroed, so mma adds 0 here and -1e30 survives
                s[nt][0] = s[nt][1] = s[nt][2] = s[nt][3] = -1e30f;
            }
        }

        // ---- S += q k^T (tf32 mma) ----
        #pragma unroll
        for (int ks = 0; ks < 4; ++ks) {
            int d = ks * 8 + tig;
            unsigned a[4];
            a[0] = __float_as_uint(qh[i0 * 32 + ((d + 4 * i0) & 31)]);
            a[1] = __float_as_uint(qh[i1 * 32 + ((d + 4 * i1) & 31)]);
            a[2] = __float_as_uint(qh[i0 * 32 + ((d + 4 + 4 * i0) & 31)]);
            a[3] = __float_as_uint(qh[i1 * 32 + ((d + 4 + 4 * i1) & 31)]);
            #pragma unroll
            for (int nt = 0; nt < 13; ++nt) {
                unsigned bb[2];
                bb[0] = __float_as_uint(kh[d * 104 + nt * 8 + gid]);
                bb[1] = __float_as_uint(kh[(d + 4) * 104 + nt * 8 + gid]);
                mma_tf32(s[nt], a, bb);
            }
        }

        // ---- softmax on fragments ----
        float m0 = -1e30f, m1 = -1e30f;
        #pragma unroll
        for (int nt = 0; nt < 13; ++nt) {
            m0 = fmaxf(m0, fmaxf(s[nt][0], s[nt][1]));
            m1 = fmaxf(m1, fmaxf(s[nt][2], s[nt][3]));
        }
        m0 = fmaxf(m0, __shfl_xor_sync(0xffffffffu, m0, 1));
        m0 = fmaxf(m0, __shfl_xor_sync(0xffffffffu, m0, 2));
        m1 = fmaxf(m1, __shfl_xor_sync(0xffffffffu, m1, 1));
        m1 = fmaxf(m1, __shfl_xor_sync(0xffffffffu, m1, 2));

        float z0 = 0.f, z1 = 0.f;
        #pragma unroll
        for (int nt = 0; nt < 13; ++nt) {
            s[nt][0] = __expf(s[nt][0] - m0);
            s[nt][1] = __expf(s[nt][1] - m0);
            s[nt][2] = __expf(s[nt][2] - m1);
            s[nt][3] = __expf(s[nt][3] - m1);
            z0 += s[nt][0] + s[nt][1];
            z1 += s[nt][2] + s[nt][3];
        }
        z0 += __shfl_xor_sync(0xffffffffu, z0, 1);
        z0 += __shfl_xor_sync(0xffffffffu, z0, 2);
        z1 += __shfl_xor_sync(0xffffffffu, z1, 1);
        z1 += __shfl_xor_sync(0xffffffffu, z1, 2);
        float inv0 = 1.f / z0, inv1 = 1.f / z1;

        // ---- O = P @ V (tf32 mma); P C-frags -> A-frags via quad shuffles ----
        float o[4][4];
        #pragma unroll
        for (int nt = 0; nt < 4; ++nt)
            #pragma unroll
            for (int e = 0; e < 4; ++e) o[nt][e] = 0.f;

        #pragma unroll
        for (int jt = 0; jt < 13; ++jt) {
            float t00 = __shfl_sync(0xffffffffu, s[jt][0], qsrc0);
            float t01 = __shfl_sync(0xffffffffu, s[jt][1], qsrc0);
            float t10 = __shfl_sync(0xffffffffu, s[jt][2], qsrc0);
            float t11 = __shfl_sync(0xffffffffu, s[jt][3], qsrc0);
            float t20 = __shfl_sync(0xffffffffu, s[jt][0], qsrc1);
            float t21 = __shfl_sync(0xffffffffu, s[jt][1], qsrc1);
            float t30 = __shfl_sync(0xffffffffu, s[jt][2], qsrc1);
            float t31 = __shfl_sync(0xffffffffu, s[jt][3], qsrc1);
            unsigned pa[4];
            CVT_TF32(pa[0], odd ? t01 : t00);   // P[gid][8jt+tig]
            CVT_TF32(pa[1], odd ? t11 : t10);   // P[gid+8][8jt+tig]
            CVT_TF32(pa[2], odd ? t21 : t20);   // P[gid][8jt+tig+4]
            CVT_TF32(pa[3], odd ? t31 : t30);   // P[gid+8][8jt+tig+4]
            #pragma unroll
            for (int nt = 0; nt < 4; ++nt) {
                unsigned bb[2];
                bb[0] = __float_as_uint(vh[(nt * 8 + gid) * 104 + jt * 8 + tig]);
                bb[1] = __float_as_uint(vh[(nt * 8 + gid) * 104 + jt * 8 + tig + 4]);
                mma_tf32(o[nt], pa, bb);
            }
        }

        // ---- store O (normalized, tf32 bits) into xs, swizzle col' = (C+4i)&127 ----
        #pragma unroll
        for (int nt = 0; nt < 4; ++nt) {
            int C = h * 32 + nt * 8 + 2 * tig;
            if (val0) {
                unsigned u0, u1;
                CVT_TF32(u0, o[nt][0] * inv0);
                CVT_TF32(u1, o[nt][1] * inv0);
                float2 w2; w2.x = __uint_as_float(u0); w2.y = __uint_as_float(u1);
                *(float2*)(xs + i0 * 128 + ((C + 4 * i0) & 127)) = w2;
            }
            if (val1) {
                unsigned u0, u1;
                CVT_TF32(u0, o[nt][2] * inv1);
                CVT_TF32(u1, o[nt][3] * inv1);
                float2 w2; w2.x = __uint_as_float(u0); w2.y = __uint_as_float(u1);
                *(float2*)(xs + i1 * 128 + ((C + 4 * i1) & 127)) = w2;
            }
        }
    }

    // ---------------- projection via tf32 mma: out = O @ Wp^T + b ----------------
    {
        float facc[7][4];
        #pragma unroll
        for (int mt = 0; mt < 7; ++mt)
            #pragma unroll
            for (int e = 0; e < 4; ++e) facc[mt][e] = 0.f;

        float preg[4];
        #pragma unroll
        for (int u = 0; u < 4; ++u) {
            int idx = tid + u * THREADS;
            int kk = idx & 15, cc = idx >> 4;
            preg[u] = proj_w[cc * 128 + kk];          // chunk 0
        }

        const int cb = ty * 8;
        for (int ch = 0; ch < 8; ++ch) {
            __syncthreads();   // first iter: covers O writes; later: wt reuse
            #pragma unroll
            for (int u = 0; u < 4; ++u) {
                int idx = tid + u * THREADS;
                int kk = idx & 15, cc = idx >> 4;
                unsigned uu; CVT_TF32(uu, preg[u]);
                wt[kk * 136 + cc] = __uint_as_float(uu);
            }
            if (ch < 7) {
                #pragma unroll
                for (int u = 0; u < 4; ++u) {
                    int idx = tid + u * THREADS;
                    int kk = idx & 15, cc = idx >> 4;
                    preg[u] = proj_w[cc * 128 + (ch + 1) * 16 + kk];
                }
            }
            __syncthreads();

            #pragma unroll
            for (int ks = 0; ks < 2; ++ks) {
                int koff = ks * 8;
                unsigned bfr[2];
                bfr[0] = __float_as_uint(wt[(koff + tig) * 136 + cb + gid]);
                bfr[1] = __float_as_uint(wt[(koff + tig + 4) * 136 + cb + gid]);
                #pragma unroll
                for (int mt = 0; mt < 7; ++mt) {
                    int i0 = mt * 16 + gid, i1 = i0 + 8;
                    int c = ch * 16 + koff + tig;
                    unsigned afr[4];
                    afr[0] = __float_as_uint(xs[i0 * 128 + ((c + 4 * i0) & 127)]);
                    afr[1] = __float_as_uint(xs[i1 * 128 + ((c + 4 * i1) & 127)]);
                    afr[2] = __float_as_uint(xs[i0 * 128 + ((c + 4 + 4 * i0) & 127)]);
                    afr[3] = __float_as_uint(xs[i1 * 128 + ((c + 4 + 4 * i1) & 127)]);
                    mma_tf32(facc[mt], afr, bfr);
                }
            }
        }

        float pb0 = proj_b[cb + 2 * tig];
        float pb1 = proj_b[cb + 2 * tig + 1];
        float* outb = out + (size_t)b * (N_TOK * CDIM);
        #pragma unroll
        for (int mt = 0; mt < 7; ++mt) {
            #pragma unroll
            for (int half = 0; half < 2; ++half) {
                int i = mt * 16 + gid + half * 8;
                if (i >= 98) continue;
                float2 v;
                v.x = facc[mt][half * 2 + 0] + pb0;
                v.y = facc[mt][half * 2 + 1] + pb1;
                *(float2*)(outb + i * 128 + cb + 2 * tig) = v;
            }
        }
    }
}

extern "C" void kernel_launch(void* const* d_in, const int* in_sizes, int n_in,
                              void* d_out, int out_size)
{
    const float* x      = (const float*)d_in[0];
    const float* mask   = (const float*)d_in[1];
    const float* qkv_w  = (const float*)d_in[2];
    const float* qkv_b  = (const float*)d_in[3];
    const float* pe     = (const float*)d_in[4];
    const float* proj_w = (const float*)d_in[5];
    const float* proj_b = (const float*)d_in[6];
    float* out = (float*)d_out;

    bias_precompute_kernel<<<(HEADS * N_TOK * N_TOK + 255) / 256, 256>>>(pe);

    const int smem_bytes = SMEM_FLOATS * sizeof(float);   // 231936
    cudaFuncSetAttribute(win_attn_kernel,
                         cudaFuncAttributeMaxDynamicSharedMemorySize, smem_bytes);

    int nwin = in_sizes[0] / (N_TOK * CDIM);              // 2048
    win_attn_kernel<<<nwin, THREADS, smem_bytes>>>(
        x, mask, qkv_w, qkv_b, proj_w, proj_b, out);
}